// round 16
// baseline (speedup 1.0000x reference)
#include <cuda_runtime.h>

// Problem constants
#define TT     25
#define FF     14
#define HH     24
#define KK     38     // FF + HH fused weight row
#define NSTEPS 13     // fwd needs t=0..12, bwd needs t=24..12
#define BTOT   65536
#define BLK    128
#define EPB    128    // elems per CTA
#define JQ     6      // j's per quarter
#define NCLS   4

typedef unsigned long long u64;

__device__ __forceinline__ u64 pack2(float lo, float hi) {
    u64 r; asm("mov.b64 %0, {%1, %2};" : "=l"(r) : "f"(lo), "f"(hi)); return r;
}
__device__ __forceinline__ u64 dup2(float v) {
    u64 r; asm("mov.b64 %0, {%1, %1};" : "=l"(r) : "f"(v)); return r;
}
__device__ __forceinline__ void unpack2(u64 v, float& lo, float& hi) {
    asm("mov.b64 {%0, %1}, %2;" : "=f"(lo), "=f"(hi) : "l"(v));
}
__device__ __forceinline__ void ffma2(u64& d, u64 a, u64 b) {
    asm("fma.rn.f32x2 %0, %1, %2, %0;" : "+l"(d) : "l"(a), "l"(b));
}

__device__ __forceinline__ float ex2f_(float x) {
    float y; asm("ex2.approx.f32 %0, %1;" : "=f"(y) : "f"(x)); return y;
}
__device__ __forceinline__ float rcpf_(float x) {
    float y; asm("rcp.approx.f32 %0, %1;" : "=f"(y) : "f"(x)); return y;
}
__device__ __forceinline__ float sigf_(float x) {
    return rcpf_(1.0f + ex2f_(-1.4426950408889634f * x));
}
// tanh(x) = 2*sigmoid(2x) - 1
__device__ __forceinline__ float tanhf_(float x) {
    float a = ex2f_(-2.8853900817779268f * x);
    float r = rcpf_(1.0f + a);
    return fmaf(2.0f, r, -1.0f);
}

__global__ __launch_bounds__(256)
void init_out_kernel(const float* __restrict__ head_b, float* __restrict__ out)
{
    const int b = blockIdx.x * blockDim.x + threadIdx.x;
    ((float4*)out)[b] = make_float4(head_b[0], head_b[1], head_b[2], head_b[3]);
}

__global__ __launch_bounds__(BLK, 3)
void lstm_kernel(const float* __restrict__ x,
                 const float* __restrict__ wih_f, const float* __restrict__ whh_f,
                 const float* __restrict__ bih_f, const float* __restrict__ bhh_f,
                 const float* __restrict__ wih_b, const float* __restrict__ whh_b,
                 const float* __restrict__ bih_b, const float* __restrict__ bhh_b,
                 const float* __restrict__ head_w, float* __restrict__ out)
{
    __shared__ ulonglong2 s_w[HH * KK];       // 14592 B {(wi,wf),(wg,wo)}
    __shared__ u64 s_bif[HH];                 //   192 B
    __shared__ u64 s_bgo[HH];                 //   192 B
    __shared__ float s_hw[NCLS * HH];         //   384 B
    __shared__ float s_h[2][EPB * 25];        // 25600 B  h ping-pong [elem][j]
    __shared__ float s_x[2][EPB * 15];        // 15360 B  x ping-pong [elem][f]

    const int tid     = threadIdx.x;
    const int lane    = tid & 31;
    const int quarter = tid >> 5;
    const int j0      = quarter * JQ;

    const int dir = blockIdx.x & 1;
    const float* wih = dir ? wih_b : wih_f;
    const float* whh = dir ? whh_b : whh_f;
    const float* bih = dir ? bih_b : bih_f;
    const float* bhh = dir ? bhh_b : bhh_f;

    for (int i = tid; i < HH * KK; i += BLK) {
        int j = i / KK, k = i % KK;
        float wi, wf, wg, wo;
        if (k < FF) {
            wi = wih[j * FF + k];
            wf = wih[(j + HH) * FF + k];
            wg = wih[(j + 2 * HH) * FF + k];
            wo = wih[(j + 3 * HH) * FF + k];
        } else {
            int kk = k - FF;
            wi = whh[j * HH + kk];
            wf = whh[(j + HH) * HH + kk];
            wg = whh[(j + 2 * HH) * HH + kk];
            wo = whh[(j + 3 * HH) * HH + kk];
        }
        ulonglong2 w; w.x = pack2(wi, wf); w.y = pack2(wg, wo);
        s_w[i] = w;
    }
    if (tid < HH) {
        int j = tid;
        s_bif[j] = pack2(bih[j] + bhh[j],                   bih[j + HH] + bhh[j + HH]);
        s_bgo[j] = pack2(bih[j + 2 * HH] + bhh[j + 2 * HH], bih[j + 3 * HH] + bhh[j + 3 * HH]);
    }
    if (tid < NCLS * HH) {
        int m = tid / HH, j = tid % HH;
        s_hw[m * HH + j] = head_w[m * (2 * HH) + dir * HH + j];
    }

    const int base = (blockIdx.x >> 1) * EPB;
    const int t0 = dir ? (TT - 1) : 0;
    const int dt = dir ? -1 : 1;

    // zero h(t=-1): this thread's (elem, j) cells cover all of s_h[0]
    #pragma unroll
    for (int m = 0; m < 4; ++m)
        #pragma unroll
        for (int q = 0; q < JQ; ++q)
            s_h[0][(lane + 32 * m) * 25 + j0 + q] = 0.f;

    // stage x(step 0) into buffer 0 (coalesced)
    {
        const int t = t0;
        #pragma unroll
        for (int i = 0; i < 7; ++i) {
            int idx = tid + i * BLK;
            int ee = idx / 7, f2 = idx - ee * 7;
            float2 v = __ldg((const float2*)(x + (size_t)(base + ee) * (TT * FF) + t * FF) + f2);
            s_x[0][ee * 15 + 2 * f2]     = v.x;
            s_x[0][ee * 15 + 2 * f2 + 1] = v.y;
        }
    }
    __syncthreads();

    float c[4][JQ];
    #pragma unroll
    for (int m = 0; m < 4; ++m)
        #pragma unroll
        for (int q = 0; q < JQ; ++q) c[m][q] = 0.f;

    int ping = 0;
    for (int s = 0; s < NSTEPS; ++s) {
        const float* xb = s_x[ping];
        const float* hb = s_h[ping];
        float* hn = s_h[ping ^ 1];

        u64 aif[4][JQ], ago[4][JQ];
        #pragma unroll
        for (int q = 0; q < JQ; ++q) {
            u64 bi = s_bif[j0 + q], bg = s_bgo[j0 + q];
            #pragma unroll
            for (int m = 0; m < 4; ++m) { aif[m][q] = bi; ago[m][q] = bg; }
        }

        // x part: one LDS.32+dup per elem per k; 6 broadcast LDS.128; 48 FFMA2
        #pragma unroll 2
        for (int k = 0; k < FF; ++k) {
            u64 d0 = dup2(xb[lane * 15 + k]);
            u64 d1 = dup2(xb[(lane + 32) * 15 + k]);
            u64 d2 = dup2(xb[(lane + 64) * 15 + k]);
            u64 d3 = dup2(xb[(lane + 96) * 15 + k]);
            #pragma unroll
            for (int q = 0; q < JQ; ++q) {
                ulonglong2 w = s_w[(j0 + q) * KK + k];
                ffma2(aif[0][q], d0, w.x); ffma2(ago[0][q], d0, w.y);
                ffma2(aif[1][q], d1, w.x); ffma2(ago[1][q], d1, w.y);
                ffma2(aif[2][q], d2, w.x); ffma2(ago[2][q], d2, w.y);
                ffma2(aif[3][q], d3, w.x); ffma2(ago[3][q], d3, w.y);
            }
        }
        // h part
        #pragma unroll 2
        for (int k = 0; k < HH; ++k) {
            u64 d0 = dup2(hb[lane * 25 + k]);
            u64 d1 = dup2(hb[(lane + 32) * 25 + k]);
            u64 d2 = dup2(hb[(lane + 64) * 25 + k]);
            u64 d3 = dup2(hb[(lane + 96) * 25 + k]);
            #pragma unroll
            for (int q = 0; q < JQ; ++q) {
                ulonglong2 w = s_w[(j0 + q) * KK + FF + k];
                ffma2(aif[0][q], d0, w.x); ffma2(ago[0][q], d0, w.y);
                ffma2(aif[1][q], d1, w.x); ffma2(ago[1][q], d1, w.y);
                ffma2(aif[2][q], d2, w.x); ffma2(ago[2][q], d2, w.y);
                ffma2(aif[3][q], d3, w.x); ffma2(ago[3][q], d3, w.y);
            }
        }

        // epilogue: activations, c update, write h(s)
        #pragma unroll
        for (int m = 0; m < 4; ++m) {
            #pragma unroll
            for (int q = 0; q < JQ; ++q) {
                float ai, af, ag, ao;
                unpack2(aif[m][q], ai, af); unpack2(ago[m][q], ag, ao);
                float ii = sigf_(ai), ff = sigf_(af), oo = sigf_(ao), gg = tanhf_(ag);
                float cn = ff * c[m][q] + ii * gg;
                c[m][q] = cn;
                hn[(lane + 32 * m) * 25 + j0 + q] = oo * tanhf_(cn);
            }
        }

        // stage x(s+1) into the other buffer
        if (s + 1 < NSTEPS) {
            const int t = t0 + dt * (s + 1);
            #pragma unroll
            for (int i = 0; i < 7; ++i) {
                int idx = tid + i * BLK;
                int ee = idx / 7, f2 = idx - ee * 7;
                float2 v = __ldg((const float2*)(x + (size_t)(base + ee) * (TT * FF) + t * FF) + f2);
                s_x[ping ^ 1][ee * 15 + 2 * f2]     = v.x;
                s_x[ping ^ 1][ee * 15 + 2 * f2 + 1] = v.y;
            }
        }
        __syncthreads();
        ping ^= 1;
    }

    // Head: final h is in s_h[ping]; thread tid handles elem row tid
    const float* hf = &s_h[ping][tid * 25];
    float p0 = 0.f, p1 = 0.f, p2 = 0.f, p3 = 0.f;
    #pragma unroll
    for (int j = 0; j < HH; ++j) {
        float v = hf[j];
        p0 += v * s_hw[j];
        p1 += v * s_hw[HH + j];
        p2 += v * s_hw[2 * HH + j];
        p3 += v * s_hw[3 * HH + j];
    }
    float* ob = out + (size_t)(base + tid) * NCLS;
    atomicAdd(ob + 0, p0); atomicAdd(ob + 1, p1);
    atomicAdd(ob + 2, p2); atomicAdd(ob + 3, p3);
}

extern "C" void kernel_launch(void* const* d_in, const int* in_sizes, int n_in,
                              void* d_out, int out_size)
{
    const float* x      = (const float*)d_in[0];
    const float* wih_f  = (const float*)d_in[1];
    const float* whh_f  = (const float*)d_in[2];
    const float* bih_f  = (const float*)d_in[3];
    const float* bhh_f  = (const float*)d_in[4];
    const float* wih_b  = (const float*)d_in[5];
    const float* whh_b  = (const float*)d_in[6];
    const float* bih_b  = (const float*)d_in[7];
    const float* bhh_b  = (const float*)d_in[8];
    const float* head_w = (const float*)d_in[9];
    const float* head_b = (const float*)d_in[10];
    float* out = (float*)d_out;

    init_out_kernel<<<BTOT / 256, 256>>>(head_b, out);
    lstm_kernel<<<(BTOT / EPB) * 2, BLK>>>(x, wih_f, whh_f, bih_f, bhh_f,
                                           wih_b, whh_b, bih_b, bhh_b,
                                           head_w, out);
}